// round 1
// baseline (speedup 1.0000x reference)
#include <cuda_runtime.h>
#include <cuda_bf16.h>

// Problem constants (from reference)
#define TPAD      192   // MAX_LEN_PAD
#define CCH       80    // C
#define NSEG      7     // MAX_NUM_SEG
#define SGRID     64    // SEG_GRID = 2*MAX_LEN_SEG... (actual useful range; see note)
#define MINSEG    19
#define NVEC      20    // float4 per row (80 floats)

// NOTE on SGRID: reference SEG_GRID = 2*MAX_LEN_SEG = 64. Slots per batch = 7*64 = 448.
// Masked slots within a segment are a strict prefix of i (both mask terms are
// monotone non-increasing in i), so compaction position = segment base + i.

__global__ __launch_bounds__(512, 3)
void interp_lnr_kernel(const float* __restrict__ x,
                       const int*   __restrict__ len_seq,
                       const float* __restrict__ scales,
                       const int*   __restrict__ len_seg_raw,
                       float*       __restrict__ out)
{
    const int b   = blockIdx.x;
    const int tid = threadIdx.x;

    __shared__ float s_scale[NSEG];
    __shared__ int   s_lenseg[NSEG];
    __shared__ int   s_off[NSEG];
    __shared__ int   s_cnt[NSEG];
    __shared__ int   s_base[NSEG];
    __shared__ int   s_total;
    __shared__ int   s_src[TPAD];
    __shared__ float s_lam[TPAD];

    if (tid < NSEG) {
        s_scale[tid]  = scales[b * NSEG + tid] + 0.5f;
        s_lenseg[tid] = len_seg_raw[b * NSEG + tid] + MINSEG;
    }
    __syncthreads();

    if (tid == 0) {
        int acc = 0;
        #pragma unroll
        for (int s = 0; s < NSEG; s++) { s_off[s] = acc; acc += s_lenseg[s]; }
    }
    __syncthreads();

    // Per-segment masked-prefix count. Both mask conditions are integer
    // comparisons on exactly-representable floats -> equivalent int compare.
    if (tid < NSEG) {
        const int   lim = min(s_lenseg[tid] - 1, len_seq[b] - 1 - s_off[tid]);
        const float sc  = s_scale[tid];
        int cnt = 0;
        if (lim > 0) {
            for (int i = 0; i < SGRID; i++) {
                // IEEE round-to-nearest f32 divide, matching the reference.
                float v = __fdiv_rn((float)i, sc);
                if (floorf(v) < (float)lim) cnt++;
                else break;   // monotone: once false, stays false
            }
        }
        s_cnt[tid] = cnt;
    }
    __syncthreads();

    if (tid == 0) {
        int acc = 0;
        #pragma unroll
        for (int s = 0; s < NSEG; s++) { s_base[s] = acc; acc += s_cnt[s]; }
        s_total = min(acc, TPAD);  // rows with pos >= 192 are dropped by the reference
    }
    __syncthreads();

    // Build compact (src_row, lam) table.
    if (tid < NSEG * SGRID) {
        const int s = tid >> 6;
        const int i = tid & 63;
        if (i < s_cnt[s]) {
            const int p = s_base[s] + i;
            if (p < TPAD) {
                float v  = __fdiv_rn((float)i, s_scale[s]);
                float fl = floorf(v);
                int src  = (int)fl + s_off[s];
                src = min(src, TPAD - 2);   // reference clips to T-2 (no-op when masked)
                s_src[p] = src;
                s_lam[p] = v - fl;
            }
        }
    }
    __syncthreads();

    const int total = s_total;
    const float4* __restrict__ xb = (const float4*)(x   + (size_t)b * TPAD * CCH);
    float4*       __restrict__ ob = (float4*)      (out + (size_t)b * TPAD * CCH);

    // Stream 192 rows x 20 float4 per batch. Rows >= total are zero.
    for (int e = tid; e < TPAD * NVEC; e += 512) {
        const int row = e / NVEC;
        const int q   = e - row * NVEC;
        float4 r;
        if (row < total) {
            const int   src = s_src[row];
            const float lam = s_lam[row];
            const float4 a = xb[src * NVEC + q];
            const float4 c = xb[(src + 1) * NVEC + q];
            r.x = fmaf(lam, c.x - a.x, a.x);
            r.y = fmaf(lam, c.y - a.y, a.y);
            r.z = fmaf(lam, c.z - a.z, a.z);
            r.w = fmaf(lam, c.w - a.w, a.w);
        } else {
            r = make_float4(0.f, 0.f, 0.f, 0.f);
        }
        ob[e] = r;
    }
}

extern "C" void kernel_launch(void* const* d_in, const int* in_sizes, int n_in,
                              void* d_out, int out_size)
{
    const float* x           = (const float*)d_in[0];
    const int*   len_seq     = (const int*)  d_in[1];
    const float* scales      = (const float*)d_in[2];
    const int*   len_seg_raw = (const int*)  d_in[3];
    float*       out         = (float*)d_out;

    const int B = in_sizes[1];  // len_seq has B elements
    interp_lnr_kernel<<<B, 512>>>(x, len_seq, scales, len_seg_raw, out);
}